// round 11
// baseline (speedup 1.0000x reference)
#include <cuda_runtime.h>
#include <cuda_bf16.h>
#include <cstdint>

// Problem: B=8, N=1024, D=768, H=12, Hd=64
__device__ float g_qkv[8192 * 2304];    // rounded tf32 bits after QKV gemm
__device__ float g_attn[8192 * 768];    // rounded tf32 bits after attention
__device__ float g_xr[8192 * 768];      // x rounded to tf32-rna
__device__ float g_wqkvr[2304 * 768];   // W_qkv rounded
__device__ float g_wprojr[768 * 768];   // W_proj rounded

// ---------------------------------------------------------------------------
// helpers
// ---------------------------------------------------------------------------
__device__ __forceinline__ uint32_t f2tf(float f) {
    uint32_t u;
    asm("cvt.rna.tf32.f32 %0, %1;" : "=r"(u) : "f"(f));
    return u;
}

__device__ __forceinline__ void mma_tf32(float c[4],
                                         const uint32_t a[4],
                                         uint32_t b0, uint32_t b1) {
    asm volatile(
        "mma.sync.aligned.m16n8k8.row.col.f32.tf32.tf32.f32 "
        "{%0,%1,%2,%3}, {%4,%5,%6,%7}, {%8,%9}, {%0,%1,%2,%3};"
        : "+f"(c[0]), "+f"(c[1]), "+f"(c[2]), "+f"(c[3])
        : "r"(a[0]), "r"(a[1]), "r"(a[2]), "r"(a[3]), "r"(b0), "r"(b1));
}

__device__ __forceinline__ void ldsm4(uint32_t r[4], uint32_t addr) {
    asm volatile("ldmatrix.sync.aligned.m8n8.x4.shared.b16 {%0,%1,%2,%3}, [%4];"
                 : "=r"(r[0]), "=r"(r[1]), "=r"(r[2]), "=r"(r[3]) : "r"(addr));
}

__device__ __forceinline__ void cpasync16(uint32_t dst, const void* src) {
    asm volatile("cp.async.cg.shared.global [%0], [%1], 16;" :: "r"(dst), "l"(src));
}
__device__ __forceinline__ void cp_commit() {
    asm volatile("cp.async.commit_group;");
}
template <int N>
__device__ __forceinline__ void cp_wait() {
    asm volatile("cp.async.wait_group %0;" :: "n"(N));
}

__device__ __forceinline__ float fast_exp2(float x) {
    float y;
    asm("ex2.approx.ftz.f32 %0, %1;" : "=f"(y) : "f"(x));
    return y;
}

// ---------------------------------------------------------------------------
// Pre-pass: elementwise round fp32 -> tf32-rna bit pattern
// ---------------------------------------------------------------------------
__global__ __launch_bounds__(256) void round_tf32_kernel(
    const float* __restrict__ in, float* __restrict__ out, int n4)
{
    const int i = blockIdx.x * 256 + threadIdx.x;
    if (i < n4) {
        const float4 v = ((const float4*)in)[i];
        uint4 r;
        r.x = f2tf(v.x); r.y = f2tf(v.y); r.z = f2tf(v.z); r.w = f2tf(v.w);
        ((uint4*)out)[i] = r;
    }
}

// ---------------------------------------------------------------------------
// TF32 GEMM v2: C[M,N] = A[M,K] @ W[N,K]^T + bias[N]
// CTA tile 256x128, 8 warps as 4(M)x2(N), warp tile 64x64 -> 8 LDSM : 32 mma
// per k-step (was 6:16). BK=32, 3-stage cp.async ring, SW128 swizzle,
// 1 CTA/SM (255-reg budget). M must be divisible by 256.
// smem/stage: A 256x128B = 32KB @0 | B 128x128B = 16KB @32768. 3 stages.
// ---------------------------------------------------------------------------
__global__ __launch_bounds__(256, 1) void gemm_tf32_kernel(
    const float* __restrict__ A, const float* __restrict__ W,
    const float* __restrict__ bias, float* __restrict__ C,
    int M, int N, int K, int roundOut)
{
    extern __shared__ uint32_t sm[];
    constexpr int STG_B = 49152;      // bytes per stage (A 32K + B 16K)

    const int tid  = threadIdx.x;
    const int lane = tid & 31;
    const int wrp  = tid >> 5;
    const int wm   = wrp & 3;         // 4 M-warps (64 rows each)
    const int wn   = wrp >> 2;        // 2 N-warps (64 cols each)
    const int g    = lane >> 2;
    const int tig  = lane & 3;

    const int m0 = blockIdx.y * 256;
    const int n0 = blockIdx.x * 128;

    const uint32_t smb = (uint32_t)__cvta_generic_to_shared(sm);

    // staging map: thread -> row0 (0..31), chunk cch (0..7).
    // A: rows row0+32i, i=0..7 (256 rows). B: rows row0+32i, i=0..3 (128 rows).
    const int row0 = tid >> 3;
    const int cch  = tid & 7;
    const uint32_t dsw = (uint32_t)((cch ^ (row0 & 7)) << 4);
    const float* srcA = A + (size_t)(m0 + row0) * K + cch * 4;
    const float* srcW = W + (size_t)(n0 + row0) * K + cch * 4;

    // ldmatrix lane bases
    const int rowA = 64 * wm + (lane & 15);              // + 16*mi
    const uint32_t rbA = (uint32_t)(rowA * 128);
    const uint32_t rxA = (uint32_t)((rowA & 7) << 4);
    const int hiA = lane >> 4;
    const int rowB = 64 * wn + (lane & 7) + ((lane >> 4) & 1) * 8;   // + 16*bj
    const uint32_t rbB = (uint32_t)(rowB * 128) + 32768;
    const uint32_t rxB = (uint32_t)((rowB & 7) << 4);
    const int hiB = (lane >> 3) & 1;

    float acc[4][8][4];
    #pragma unroll
    for (int i = 0; i < 4; i++)
        #pragma unroll
        for (int j = 0; j < 8; j++)
            #pragma unroll
            for (int c = 0; c < 4; c++) acc[i][j][c] = 0.0f;

    const int NK = K >> 5;   // 24

    // prologue: fill stages 0,1
    #pragma unroll
    for (int s = 0; s < 2; s++) {
        const uint32_t sb = smb + s * STG_B;
        #pragma unroll
        for (int i = 0; i < 8; i++) {
            const uint32_t d = sb + (uint32_t)((row0 + 32 * i) * 128) + dsw;
            cpasync16(d, srcA + s * 32 + (size_t)(32 * i) * K);
        }
        #pragma unroll
        for (int i = 0; i < 4; i++) {
            const uint32_t d = sb + 32768 + (uint32_t)((row0 + 32 * i) * 128) + dsw;
            cpasync16(d, srcW + s * 32 + (size_t)(32 * i) * K);
        }
        cp_commit();
    }

    int stage = 0;
    for (int t = 0; t < NK; t++) {
        cp_wait<1>();
        __syncthreads();

        if (t + 2 < NK) {
            const int s = (stage + 2 >= 3) ? stage - 1 : stage + 2;
            const uint32_t sb = smb + s * STG_B;
            const int kofs = (t + 2) * 32;
            #pragma unroll
            for (int i = 0; i < 8; i++) {
                const uint32_t d = sb + (uint32_t)((row0 + 32 * i) * 128) + dsw;
                cpasync16(d, srcA + kofs + (size_t)(32 * i) * K);
            }
            #pragma unroll
            for (int i = 0; i < 4; i++) {
                const uint32_t d = sb + 32768 + (uint32_t)((row0 + 32 * i) * 128) + dsw;
                cpasync16(d, srcW + kofs + (size_t)(32 * i) * K);
            }
        }
        cp_commit();

        const uint32_t sb = smb + stage * STG_B;
        #pragma unroll
        for (int ks = 0; ks < 4; ks++) {
            const uint32_t ca = ((uint32_t)((2 * ks + hiA) << 4)) ^ rxA;
            const uint32_t cb = ((uint32_t)((2 * ks + hiB) << 4)) ^ rxB;
            uint32_t a[4][4];
            #pragma unroll
            for (int mi = 0; mi < 4; mi++)
                ldsm4(a[mi], sb + rbA + mi * 2048 + ca);
            #pragma unroll
            for (int bj = 0; bj < 4; bj++) {
                uint32_t b[4];
                ldsm4(b, sb + rbB + bj * 2048 + cb);
                #pragma unroll
                for (int mi = 0; mi < 4; mi++) {
                    mma_tf32(acc[mi][2 * bj],     a[mi], b[0], b[1]);
                    mma_tf32(acc[mi][2 * bj + 1], a[mi], b[2], b[3]);
                }
            }
        }
        stage = (stage + 1 >= 3) ? 0 : stage + 1;
    }

    // epilogue: bias + store
    #pragma unroll
    for (int j = 0; j < 8; j++) {
        const int col = n0 + 64 * wn + 8 * j + 2 * tig;
        const float b0 = bias[col];
        const float b1 = bias[col + 1];
        #pragma unroll
        for (int mi = 0; mi < 4; mi++) {
            const int row = m0 + 64 * wm + 16 * mi + g;
            float v0 = acc[mi][j][0] + b0, v1 = acc[mi][j][1] + b1;
            float v2 = acc[mi][j][2] + b0, v3 = acc[mi][j][3] + b1;
            if (roundOut) {
                v0 = __uint_as_float(f2tf(v0));
                v1 = __uint_as_float(f2tf(v1));
                v2 = __uint_as_float(f2tf(v2));
                v3 = __uint_as_float(f2tf(v3));
            }
            *(float2*)&C[(size_t)row * N + col]       = make_float2(v0, v1);
            *(float2*)&C[(size_t)(row + 8) * N + col] = make_float2(v2, v3);
        }
    }
}

// ---------------------------------------------------------------------------
// TF32 flash attention (R9 version — best measured).
// 256 threads (8 warps x 16 q-rows), 128 queries/block, split 64-key tiles,
// P in registers via key permutation sigma(2t+e)=t+4e baked into Vt.
// ---------------------------------------------------------------------------
__global__ __launch_bounds__(256, 2) void attn_tf32_kernel()
{
    extern __shared__ uint32_t sm[];
    constexpr int LDA = 68;
    constexpr int VT_U32 = 17408;
    constexpr int STG_U32 = 4352;
    constexpr int STG_BYTE = 17408;

    const int tid  = threadIdx.x;
    const int lane = tid & 31;
    const int wrp  = tid >> 5;
    const int g    = lane >> 2;
    const int tig  = lane & 3;

    const int qtile = blockIdx.x & 7;
    const int bh    = blockIdx.x >> 3;
    const int h     = bh % 12;
    const int b     = bh / 12;
    const int q0    = qtile * 128;
    const int mb    = 16 * wrp;

    const uint32_t smb = (uint32_t)__cvta_generic_to_shared(sm);
    const uint32_t qaBase = smb + (((mb + (lane & 15)) * LDA + (lane >> 4) * 4) << 2);
    const uint32_t bRow = (((lane & 7) + ((lane >> 4) & 1) * 8) * LDA + ((lane >> 3) & 1) * 4) << 2;
    const uint32_t kbBase = smb + 34816 + bRow;
    const uint32_t vbBase = smb + 69632 + bRow;

    const size_t tokBase = (size_t)(b * 1024) * 2304 + h * 64;

    #pragma unroll
    for (int it = 0; it < 8; it++) {
        const int e   = tid + it * 256;
        const int row = e >> 4;
        const int c4  = (e & 15) * 4;
        *(float4*)&sm[row * LDA + c4] =
            *(const float4*)&g_qkv[tokBase + (size_t)(q0 + row) * 2304 + c4];
    }

    float O[8][4];
    #pragma unroll
    for (int j = 0; j < 8; j++)
        #pragma unroll
        for (int c = 0; c < 4; c++) O[j][c] = 0.0f;
    float mrun[2] = {-1e30f, -1e30f}, lrun[2] = {0.0f, 0.0f};

    const float SC = 0.18033688011112042f;   // 0.125 * log2(e)

    const int vhd  = tid & 63;
    const int vkg  = tid >> 6;

    #pragma unroll
    for (int it = 0; it < 4; it++) {
        const int e   = tid + it * 256;
        const int key = e >> 4;
        const int c   = e & 15;
        cpasync16(smb + 34816 + (uint32_t)((key * LDA + c * 4) << 2),
                  &g_qkv[tokBase + (size_t)key * 2304 + 768 + c * 4]);
    }
    cp_commit();
    #pragma unroll
    for (int it = 0; it < 4; it++) {
        const int kg  = vkg + it * 4;
        const int grp = kg >> 1;
        const int ee  = kg & 1;
        const size_t vb = tokBase + (size_t)(8 * grp + ee) * 2304 + 1536 + vhd;
        float4 v;
        v.x = g_qkv[vb];
        v.y = g_qkv[vb + 2 * 2304];
        v.z = g_qkv[vb + 4 * 2304];
        v.w = g_qkv[vb + 6 * 2304];
        *(float4*)&sm[VT_U32 + vhd * LDA + 8 * grp + 4 * ee] = v;
    }

    for (int t = 0; t < 16; t++) {
        const int cur = t & 1;
        const int nxt = cur ^ 1;
        const int tn  = (t + 1 < 16) ? t + 1 : 15;

        cp_wait<0>();
        __syncthreads();

        // prefetch next K (async) + next-V gather loads
        const size_t nb = tokBase + (size_t)(tn * 64) * 2304;
        #pragma unroll
        for (int it = 0; it < 4; it++) {
            const int e   = tid + it * 256;
            const int key = e >> 4;
            const int c   = e & 15;
            cpasync16(smb + 34816 + (uint32_t)(nxt * STG_BYTE) +
                          (uint32_t)((key * LDA + c * 4) << 2),
                      &g_qkv[nb + (size_t)key * 2304 + 768 + c * 4]);
        }
        cp_commit();
        float4 gv[4];
        #pragma unroll
        for (int it = 0; it < 4; it++) {
            const int kg  = vkg + it * 4;
            const int grp = kg >> 1;
            const int ee  = kg & 1;
            const size_t vb = nb + (size_t)(8 * grp + ee) * 2304 + 1536 + vhd;
            gv[it].x = g_qkv[vb];
            gv[it].y = g_qkv[vb + 2 * 2304];
            gv[it].z = g_qkv[vb + 4 * 2304];
            gv[it].w = g_qkv[vb + 6 * 2304];
        }

        const uint32_t kb  = kbBase + cur * STG_BYTE;
        const uint32_t vbs = vbBase + cur * STG_BYTE;

        float s[8][4];
        #pragma unroll
        for (int j = 0; j < 8; j++)
            #pragma unroll
            for (int c = 0; c < 4; c++) s[j][c] = 0.0f;

        // ---- S_A: keys 0..31 ----
        #pragma unroll
        for (int ks = 0; ks < 8; ks++) {
            uint32_t qa[4];
            ldsm4(qa, qaBase + ks * 32);
            #pragma unroll
            for (int jj = 0; jj < 2; jj++) {
                uint32_t bfr[4];
                ldsm4(bfr, kb + ks * 32 + jj * (16 * LDA * 4));
                mma_tf32(s[2 * jj],     qa, bfr[0], bfr[1]);
                mma_tf32(s[2 * jj + 1], qa, bfr[2], bfr[3]);
            }
        }

        // ---- softmax_A (full, incl. O-rescale) — interleaves with S_B ----
        #pragma unroll
        for (int hf = 0; hf < 2; hf++) {
            float mx = -1e30f;
            #pragma unroll
            for (int j = 0; j < 4; j++) {
                s[j][2 * hf]     *= SC;
                s[j][2 * hf + 1] *= SC;
                mx = fmaxf(mx, fmaxf(s[j][2 * hf], s[j][2 * hf + 1]));
            }
            mx = fmaxf(mx, __shfl_xor_sync(0xffffffffu, mx, 1));
            mx = fmaxf(mx, __shfl_xor_sync(0xffffffffu, mx, 2));
            const float nm   = fmaxf(mrun[hf], mx);
            const float corr = fast_exp2(mrun[hf] - nm);
            mrun[hf] = nm;
            float sum = 0.0f;
            #pragma unroll
            for (int j = 0; j < 4; j++) {
                const float p0 = fast_exp2(s[j][2 * hf] - nm);
                const float p1 = fast_exp2(s[j][2 * hf + 1] - nm);
                s[j][2 * hf] = p0;
                s[j][2 * hf + 1] = p1;
                sum += p0 + p1;
            }
            sum += __shfl_xor_sync(0xffffffffu, sum, 1);
            sum += __shfl_xor_sync(0xffffffffu, sum, 2);
            lrun[hf] = lrun[hf] * corr + sum;
            #pragma unroll
            for (int j = 0; j < 8; j++) {
                O[j][2 * hf]     *= corr;
                O[j][2 * hf + 1] *= corr;
            }
        }

        // ---- S_B: keys 32..63 ----
        #pragma unroll
        for (int ks = 0; ks < 8; ks++) {
            uint32_t qa[4];
            ldsm4(qa, qaBase + ks * 32);
            #pragma unroll
            for (int jj = 2; jj < 4; jj++) {
                uint32_t bfr[4];
                ldsm4(bfr, kb + ks * 32 + jj * (16 * LDA * 4));
                mma_tf32(s[2 * jj],     qa, bfr[0], bfr[1]);
                mma_tf32(s[2 * jj + 1], qa, bfr[2], bfr[3]);
            }
        }

        // ---- store next-V transpose ----
        #pragma unroll
        for (int it = 0; it < 4; it++) {
            const int kg  = vkg + it * 4;
            const int grp = kg >> 1;
            const int ee  = kg & 1;
            *(float4*)&sm[VT_U32 + nxt * STG_U32 + vhd * LDA + 8 * grp + 4 * ee] = gv[it];
        }

        // ---- softmax_B compute (no O-rescale yet) — interleaves with PV_A ----
        float corrB[2];
        #pragma unroll
        for (int hf = 0; hf < 2; hf++) {
            float mx = -1e30f;
            #pragma unroll
            for (int j = 4; j < 8; j++) {
                s[j][2 * hf]     *= SC;
                s[j][2 * hf + 1] *= SC;
                mx = fmaxf(mx, fmaxf(s[j][2 * hf], s[j][2 * hf + 1]));
            }
            mx = fmaxf(mx, __shfl_xor_sync(0xffffffffu, mx, 1));
            mx = fmaxf(mx, __shfl_xor_sync(0xffffffffu, mx, 2));
            const float nm = fmaxf(mrun[hf], mx);
            corrB[hf] = fast_exp2(mrun[hf] - nm);
            mrun[hf] = nm;
            float sum = 0.0f;
            #pragma unroll
            for (int j = 4; j < 8; j++) {
                const float p0 = fast_exp2(s[j][2 * hf] - nm);
                const float p1 = fast_exp2(s[j][2 * hf + 1] - nm);
                s[j][2 * hf] = p0;
                s[j][2 * hf + 1] = p1;
                sum += p0 + p1;
            }
            sum += __shfl_xor_sync(0xffffffffu, sum, 1);
            sum += __shfl_xor_sync(0xffffffffu, sum, 2);
            lrun[hf] = lrun[hf] * corrB[hf] + sum;
        }

        // ---- PV_A: O += P_A @ V[0:32] ----
        #pragma unroll
        for (int j = 0; j < 4; j++) {
            uint32_t pa[4];
            pa[0] = f2tf(s[j][0]);
            pa[1] = f2tf(s[j][2]);
            pa[2] = f2tf(s[j][1]);
            pa[3] = f2tf(s[j][3]);
            #pragma unroll
            for (int jj = 0; jj < 4; jj++) {
                uint32_t bfr[4];
                ldsm4(bfr, vbs + j * 32 + jj * (16 * LDA * 4));
                mma_tf32(O[2 * jj],     pa, bfr[0], bfr[1]);
                mma_tf32(O[2 * jj + 1], pa, bfr[2], bfr[3]);
            }
        }

        // ---- O *= corr_B ----
        #pragma unroll
        for (int hf = 0; hf < 2; hf++)
            #pragma unroll
            for (int j = 0; j < 8; j++) {
                O[j][2 * hf]     *= corrB[hf];
                O[j][2 * hf + 1] *= corrB[hf];
            }

        // ---- PV_B: O += P_B @ V[32:64] ----
        #pragma unroll
        for (int j = 4; j < 8; j++) {
            uint32_t pa[4];
            pa[0] = f2tf(s[j][0]);
            pa[1] = f2tf(s[j][2]);
            pa[2] = f2tf(s[j][1]);
            pa[3] = f2tf(s[j][3]);
            #pragma unroll
            for (int jj = 0; jj < 4; jj++) {
                uint32_t bfr[4];
                ldsm4(bfr, vbs + j * 32 + jj * (16 * LDA * 4));
                mma_tf32(O[2 * jj],     pa, bfr[0], bfr[1]);
                mma_tf32(O[2 * jj + 1], pa, bfr[2], bfr[3]);
            }
        }
    }

    // normalize + store (rounded for the proj GEMM)
    #pragma unroll
    for (int hf = 0; hf < 2; hf++) {
        const float linv = 1.0f / lrun[hf];
        const int row = q0 + mb + g + 8 * hf;
        #pragma unroll
        for (int j = 0; j < 8; j++) {
            const int col = h * 64 + 8 * j + 2 * tig;
            *(float2*)&g_attn[(size_t)(b * 1024 + row) * 768 + col] =
                make_float2(__uint_as_float(f2tf(O[j][2 * hf] * linv)),
                            __uint_as_float(f2tf(O[j][2 * hf + 1] * linv)));
        }
    }
}

// ---------------------------------------------------------------------------
// Launch
// ---------------------------------------------------------------------------
extern "C" void kernel_launch(void* const* d_in, const int* in_sizes, int n_in,
                              void* d_out, int out_size)
{
    const float* x     = (const float*)d_in[0];
    const float* Wqkv  = (const float*)d_in[1];
    const float* bqkv  = (const float*)d_in[2];
    const float* Wproj = (const float*)d_in[3];
    const float* bproj = (const float*)d_in[4];
    float* out = (float*)d_out;

    float *qkv, *attn, *xr, *wqkvr, *wprojr;
    cudaGetSymbolAddress((void**)&qkv,    g_qkv);
    cudaGetSymbolAddress((void**)&attn,   g_attn);
    cudaGetSymbolAddress((void**)&xr,     g_xr);
    cudaGetSymbolAddress((void**)&wqkvr,  g_wqkvr);
    cudaGetSymbolAddress((void**)&wprojr, g_wprojr);

    const int gemm_smem = 3 * 49152;                        // 147456 B
    const int attn_smem = 68 * (128 + 128 + 128) * 4;       // 104448 B
    static bool attr_done = false;
    if (!attr_done) {
        cudaFuncSetAttribute(gemm_tf32_kernel,
                             cudaFuncAttributeMaxDynamicSharedMemorySize, gemm_smem);
        cudaFuncSetAttribute(attn_tf32_kernel,
                             cudaFuncAttributeMaxDynamicSharedMemorySize, attn_smem);
        attr_done = true;
    }

    // 0) round inputs to tf32-rna
    round_tf32_kernel<<<(8192 * 768 / 4 + 255) / 256, 256>>>(x, xr, 8192 * 768 / 4);
    round_tf32_kernel<<<(2304 * 768 / 4 + 255) / 256, 256>>>(Wqkv, wqkvr, 2304 * 768 / 4);
    round_tf32_kernel<<<(768 * 768 / 4 + 255) / 256, 256>>>(Wproj, wprojr, 768 * 768 / 4);

    {   // QKV: [8192,768] @ [2304,768]^T + b   (round outputs for attention)
        dim3 grid(2304 / 128, 8192 / 256);
        gemm_tf32_kernel<<<grid, 256, gemm_smem>>>(xr, wqkvr, bqkv, qkv, 8192, 2304, 768, 1);
    }
    {   // attention
        attn_tf32_kernel<<<768, 256, attn_smem>>>();
    }
    {   // proj: [8192,768] @ [768,768]^T + b   (final output, no rounding)
        dim3 grid(768 / 128, 8192 / 256);
        gemm_tf32_kernel<<<grid, 256, gemm_smem>>>(attn, wprojr, bproj, out, 8192, 768, 768, 0);
    }
}

// round 12
// speedup vs baseline: 1.0574x; 1.0574x over previous
#include <cuda_runtime.h>
#include <cuda_bf16.h>
#include <cstdint>

// Problem: B=8, N=1024, D=768, H=12, Hd=64
__device__ float g_qkv[8192 * 2304];    // rounded tf32 bits after QKV gemm
__device__ float g_attn[8192 * 768];    // rounded tf32 bits after attention
__device__ float g_xr[8192 * 768];      // x rounded to tf32-rna
__device__ float g_wqkvr[2304 * 768];   // W_qkv rounded
__device__ float g_wprojr[768 * 768];   // W_proj rounded

// ---------------------------------------------------------------------------
// helpers
// ---------------------------------------------------------------------------
__device__ __forceinline__ uint32_t f2tf(float f) {
    uint32_t u;
    asm("cvt.rna.tf32.f32 %0, %1;" : "=r"(u) : "f"(f));
    return u;
}

__device__ __forceinline__ void mma_tf32(float c[4],
                                         const uint32_t a[4],
                                         uint32_t b0, uint32_t b1) {
    asm volatile(
        "mma.sync.aligned.m16n8k8.row.col.f32.tf32.tf32.f32 "
        "{%0,%1,%2,%3}, {%4,%5,%6,%7}, {%8,%9}, {%0,%1,%2,%3};"
        : "+f"(c[0]), "+f"(c[1]), "+f"(c[2]), "+f"(c[3])
        : "r"(a[0]), "r"(a[1]), "r"(a[2]), "r"(a[3]), "r"(b0), "r"(b1));
}

__device__ __forceinline__ void ldsm4(uint32_t r[4], uint32_t addr) {
    asm volatile("ldmatrix.sync.aligned.m8n8.x4.shared.b16 {%0,%1,%2,%3}, [%4];"
                 : "=r"(r[0]), "=r"(r[1]), "=r"(r[2]), "=r"(r[3]) : "r"(addr));
}

__device__ __forceinline__ void cpasync16(uint32_t dst, const void* src) {
    asm volatile("cp.async.cg.shared.global [%0], [%1], 16;" :: "r"(dst), "l"(src));
}
__device__ __forceinline__ void cp_commit() {
    asm volatile("cp.async.commit_group;");
}
template <int N>
__device__ __forceinline__ void cp_wait() {
    asm volatile("cp.async.wait_group %0;" :: "n"(N));
}

__device__ __forceinline__ float fast_exp2(float x) {
    float y;
    asm("ex2.approx.ftz.f32 %0, %1;" : "=f"(y) : "f"(x));
    return y;
}

// ---------------------------------------------------------------------------
// Pre-pass: elementwise round fp32 -> tf32-rna bit pattern
// ---------------------------------------------------------------------------
__global__ __launch_bounds__(256) void round_tf32_kernel(
    const float* __restrict__ in, float* __restrict__ out, int n4)
{
    const int i = blockIdx.x * 256 + threadIdx.x;
    if (i < n4) {
        const float4 v = ((const float4*)in)[i];
        uint4 r;
        r.x = f2tf(v.x); r.y = f2tf(v.y); r.z = f2tf(v.z); r.w = f2tf(v.w);
        ((uint4*)out)[i] = r;
    }
}

// ---------------------------------------------------------------------------
// TF32 GEMM: C[M,N] = A[M,K] @ W[N,K]^T + bias[N]
// R5 configuration (proven 159-160 us): 128x128 CTA tile, warp 32x64,
// BK=32, 3-stage cp.async, SW128 swizzle, 2 CTAs/SM.
// ---------------------------------------------------------------------------
__global__ __launch_bounds__(256, 2) void gemm_tf32_kernel(
    const float* __restrict__ A, const float* __restrict__ W,
    const float* __restrict__ bias, float* __restrict__ C,
    int M, int N, int K, int roundOut)
{
    extern __shared__ uint32_t sm[];
    constexpr int STG_B = 32768;

    const int tid  = threadIdx.x;
    const int lane = tid & 31;
    const int wrp  = tid >> 5;
    const int wm   = wrp & 3;
    const int wn   = wrp >> 2;
    const int g    = lane >> 2;
    const int tig  = lane & 3;

    const int m0 = blockIdx.y * 128;
    const int n0 = blockIdx.x * 128;

    const uint32_t smb = (uint32_t)__cvta_generic_to_shared(sm);

    const int row0 = tid >> 3;
    const int cch  = tid & 7;
    const uint32_t dsw = (uint32_t)((cch ^ (row0 & 7)) << 4);
    const float* srcA = A + (size_t)(m0 + row0) * K + cch * 4;
    const float* srcW = W + (size_t)(n0 + row0) * K + cch * 4;

    const int rowA = 32 * wm + (lane & 15);
    const uint32_t rbA = (uint32_t)(rowA * 128);
    const uint32_t rxA = (uint32_t)((rowA & 7) << 4);
    const int hiA = lane >> 4;
    const int rowB = 64 * wn + (lane & 7) + ((lane >> 4) & 1) * 8;
    const uint32_t rbB = (uint32_t)(rowB * 128);
    const uint32_t rxB = (uint32_t)((rowB & 7) << 4);
    const int hiB = (lane >> 3) & 1;

    float acc[2][8][4];
    #pragma unroll
    for (int i = 0; i < 2; i++)
        #pragma unroll
        for (int j = 0; j < 8; j++)
            #pragma unroll
            for (int c = 0; c < 4; c++) acc[i][j][c] = 0.0f;

    const int NK = K >> 5;

    #pragma unroll
    for (int s = 0; s < 2; s++) {
        const uint32_t sb = smb + s * STG_B;
        #pragma unroll
        for (int i = 0; i < 4; i++) {
            const uint32_t d = sb + (uint32_t)((row0 + 32 * i) * 128) + dsw;
            cpasync16(d,         srcA + s * 32 + (size_t)(32 * i) * K);
            cpasync16(d + 16384, srcW + s * 32 + (size_t)(32 * i) * K);
        }
        cp_commit();
    }

    int stage = 0;
    for (int t = 0; t < NK; t++) {
        cp_wait<1>();
        __syncthreads();

        if (t + 2 < NK) {
            const int s = (stage + 2 >= 3) ? stage - 1 : stage + 2;
            const uint32_t sb = smb + s * STG_B;
            const int kofs = (t + 2) * 32;
            #pragma unroll
            for (int i = 0; i < 4; i++) {
                const uint32_t d = sb + (uint32_t)((row0 + 32 * i) * 128) + dsw;
                cpasync16(d,         srcA + kofs + (size_t)(32 * i) * K);
                cpasync16(d + 16384, srcW + kofs + (size_t)(32 * i) * K);
            }
        }
        cp_commit();

        const uint32_t sA = smb + stage * STG_B;
        const uint32_t sB = sA + 16384;
        #pragma unroll
        for (int ks = 0; ks < 4; ks++) {
            uint32_t a0[4], a1[4];
            const uint32_t ca = ((uint32_t)((2 * ks + hiA) << 4)) ^ rxA;
            ldsm4(a0, sA + rbA + ca);
            ldsm4(a1, sA + rbA + ca + 2048);
            const uint32_t cb = ((uint32_t)((2 * ks + hiB) << 4)) ^ rxB;
            #pragma unroll
            for (int jj = 0; jj < 4; jj++) {
                uint32_t b[4];
                ldsm4(b, sB + rbB + jj * 2048 + cb);
                mma_tf32(acc[0][2 * jj],     a0, b[0], b[1]);
                mma_tf32(acc[1][2 * jj],     a1, b[0], b[1]);
                mma_tf32(acc[0][2 * jj + 1], a0, b[2], b[3]);
                mma_tf32(acc[1][2 * jj + 1], a1, b[2], b[3]);
            }
        }
        stage = (stage + 1 >= 3) ? 0 : stage + 1;
    }

    #pragma unroll
    for (int j = 0; j < 8; j++) {
        const int col = n0 + 64 * wn + 8 * j + 2 * tig;
        const float b0 = bias[col];
        const float b1 = bias[col + 1];
        #pragma unroll
        for (int i = 0; i < 2; i++) {
            const int row = m0 + 32 * wm + 16 * i + g;
            float v0 = acc[i][j][0] + b0, v1 = acc[i][j][1] + b1;
            float v2 = acc[i][j][2] + b0, v3 = acc[i][j][3] + b1;
            if (roundOut) {
                v0 = __uint_as_float(f2tf(v0));
                v1 = __uint_as_float(f2tf(v1));
                v2 = __uint_as_float(f2tf(v2));
                v3 = __uint_as_float(f2tf(v3));
            }
            *(float2*)&C[(size_t)row * N + col]       = make_float2(v0, v1);
            *(float2*)&C[(size_t)(row + 8) * N + col] = make_float2(v2, v3);
        }
    }
}

// ---------------------------------------------------------------------------
// TF32 flash attention v6: R9 split-tile overlap + persistent Q fragments.
// Q frags (qa[8][4], 32 regs) loaded ONCE before the key loop — removes
// 16 ldsm4 per tile per warp (25% of the tile's smem loads).
// Everything else identical to R9 (best measured ordering).
// ---------------------------------------------------------------------------
__global__ __launch_bounds__(256, 2) void attn_tf32_kernel()
{
    extern __shared__ uint32_t sm[];
    constexpr int LDA = 68;
    constexpr int VT_U32 = 17408;
    constexpr int STG_U32 = 4352;
    constexpr int STG_BYTE = 17408;

    const int tid  = threadIdx.x;
    const int lane = tid & 31;
    const int wrp  = tid >> 5;
    const int g    = lane >> 2;
    const int tig  = lane & 3;

    const int qtile = blockIdx.x & 7;
    const int bh    = blockIdx.x >> 3;
    const int h     = bh % 12;
    const int b     = bh / 12;
    const int q0    = qtile * 128;
    const int mb    = 16 * wrp;

    const uint32_t smb = (uint32_t)__cvta_generic_to_shared(sm);
    const uint32_t qaBase = smb + (((mb + (lane & 15)) * LDA + (lane >> 4) * 4) << 2);
    const uint32_t bRow = (((lane & 7) + ((lane >> 4) & 1) * 8) * LDA + ((lane >> 3) & 1) * 4) << 2;
    const uint32_t kbBase = smb + 34816 + bRow;
    const uint32_t vbBase = smb + 69632 + bRow;

    const size_t tokBase = (size_t)(b * 1024) * 2304 + h * 64;

    // stage Q [128][64] to smem, then hoist fragments into registers (once)
    #pragma unroll
    for (int it = 0; it < 8; it++) {
        const int e   = tid + it * 256;
        const int row = e >> 4;
        const int c4  = (e & 15) * 4;
        *(float4*)&sm[row * LDA + c4] =
            *(const float4*)&g_qkv[tokBase + (size_t)(q0 + row) * 2304 + c4];
    }
    __syncthreads();
    uint32_t qa[8][4];
    #pragma unroll
    for (int ks = 0; ks < 8; ks++) ldsm4(qa[ks], qaBase + ks * 32);

    float O[8][4];
    #pragma unroll
    for (int j = 0; j < 8; j++)
        #pragma unroll
        for (int c = 0; c < 4; c++) O[j][c] = 0.0f;
    float mrun[2] = {-1e30f, -1e30f}, lrun[2] = {0.0f, 0.0f};

    const float SC = 0.18033688011112042f;   // 0.125 * log2(e)

    const int vhd  = tid & 63;
    const int vkg  = tid >> 6;

    // prologue: K0 via cp.async, V0 gather-transpose
    #pragma unroll
    for (int it = 0; it < 4; it++) {
        const int e   = tid + it * 256;
        const int key = e >> 4;
        const int c   = e & 15;
        cpasync16(smb + 34816 + (uint32_t)((key * LDA + c * 4) << 2),
                  &g_qkv[tokBase + (size_t)key * 2304 + 768 + c * 4]);
    }
    cp_commit();
    #pragma unroll
    for (int it = 0; it < 4; it++) {
        const int kg  = vkg + it * 4;
        const int grp = kg >> 1;
        const int ee  = kg & 1;
        const size_t vb = tokBase + (size_t)(8 * grp + ee) * 2304 + 1536 + vhd;
        float4 v;
        v.x = g_qkv[vb];
        v.y = g_qkv[vb + 2 * 2304];
        v.z = g_qkv[vb + 4 * 2304];
        v.w = g_qkv[vb + 6 * 2304];
        *(float4*)&sm[VT_U32 + vhd * LDA + 8 * grp + 4 * ee] = v;
    }

    for (int t = 0; t < 16; t++) {
        const int cur = t & 1;
        const int nxt = cur ^ 1;
        const int tn  = (t + 1 < 16) ? t + 1 : 15;

        cp_wait<0>();
        __syncthreads();

        // prefetch next K (async) + next-V gather loads
        const size_t nb = tokBase + (size_t)(tn * 64) * 2304;
        #pragma unroll
        for (int it = 0; it < 4; it++) {
            const int e   = tid + it * 256;
            const int key = e >> 4;
            const int c   = e & 15;
            cpasync16(smb + 34816 + (uint32_t)(nxt * STG_BYTE) +
                          (uint32_t)((key * LDA + c * 4) << 2),
                      &g_qkv[nb + (size_t)key * 2304 + 768 + c * 4]);
        }
        cp_commit();
        float4 gv[4];
        #pragma unroll
        for (int it = 0; it < 4; it++) {
            const int kg  = vkg + it * 4;
            const int grp = kg >> 1;
            const int ee  = kg & 1;
            const size_t vb = nb + (size_t)(8 * grp + ee) * 2304 + 1536 + vhd;
            gv[it].x = g_qkv[vb];
            gv[it].y = g_qkv[vb + 2 * 2304];
            gv[it].z = g_qkv[vb + 4 * 2304];
            gv[it].w = g_qkv[vb + 6 * 2304];
        }

        const uint32_t kb  = kbBase + cur * STG_BYTE;
        const uint32_t vbs = vbBase + cur * STG_BYTE;

        float s[8][4];
        #pragma unroll
        for (int j = 0; j < 8; j++)
            #pragma unroll
            for (int c = 0; c < 4; c++) s[j][c] = 0.0f;

        // ---- S_A: keys 0..31 ----
        #pragma unroll
        for (int ks = 0; ks < 8; ks++) {
            #pragma unroll
            for (int jj = 0; jj < 2; jj++) {
                uint32_t bfr[4];
                ldsm4(bfr, kb + ks * 32 + jj * (16 * LDA * 4));
                mma_tf32(s[2 * jj],     qa[ks], bfr[0], bfr[1]);
                mma_tf32(s[2 * jj + 1], qa[ks], bfr[2], bfr[3]);
            }
        }

        // ---- softmax_A (full, incl. O-rescale) — interleaves with S_B ----
        #pragma unroll
        for (int hf = 0; hf < 2; hf++) {
            float mx = -1e30f;
            #pragma unroll
            for (int j = 0; j < 4; j++) {
                s[j][2 * hf]     *= SC;
                s[j][2 * hf + 1] *= SC;
                mx = fmaxf(mx, fmaxf(s[j][2 * hf], s[j][2 * hf + 1]));
            }
            mx = fmaxf(mx, __shfl_xor_sync(0xffffffffu, mx, 1));
            mx = fmaxf(mx, __shfl_xor_sync(0xffffffffu, mx, 2));
            const float nm   = fmaxf(mrun[hf], mx);
            const float corr = fast_exp2(mrun[hf] - nm);
            mrun[hf] = nm;
            float sum = 0.0f;
            #pragma unroll
            for (int j = 0; j < 4; j++) {
                const float p0 = fast_exp2(s[j][2 * hf] - nm);
                const float p1 = fast_exp2(s[j][2 * hf + 1] - nm);
                s[j][2 * hf] = p0;
                s[j][2 * hf + 1] = p1;
                sum += p0 + p1;
            }
            sum += __shfl_xor_sync(0xffffffffu, sum, 1);
            sum += __shfl_xor_sync(0xffffffffu, sum, 2);
            lrun[hf] = lrun[hf] * corr + sum;
            #pragma unroll
            for (int j = 0; j < 8; j++) {
                O[j][2 * hf]     *= corr;
                O[j][2 * hf + 1] *= corr;
            }
        }

        // ---- S_B: keys 32..63 ----
        #pragma unroll
        for (int ks = 0; ks < 8; ks++) {
            #pragma unroll
            for (int jj = 2; jj < 4; jj++) {
                uint32_t bfr[4];
                ldsm4(bfr, kb + ks * 32 + jj * (16 * LDA * 4));
                mma_tf32(s[2 * jj],     qa[ks], bfr[0], bfr[1]);
                mma_tf32(s[2 * jj + 1], qa[ks], bfr[2], bfr[3]);
            }
        }

        // ---- store next-V transpose ----
        #pragma unroll
        for (int it = 0; it < 4; it++) {
            const int kg  = vkg + it * 4;
            const int grp = kg >> 1;
            const int ee  = kg & 1;
            *(float4*)&sm[VT_U32 + nxt * STG_U32 + vhd * LDA + 8 * grp + 4 * ee] = gv[it];
        }

        // ---- softmax_B compute (no O-rescale yet) — interleaves with PV_A ----
        float corrB[2];
        #pragma unroll
        for (int hf = 0; hf < 2; hf++) {
            float mx = -1e30f;
            #pragma unroll
            for (int j = 4; j < 8; j++) {
                s[j][2 * hf]     *= SC;
                s[j][2 * hf + 1] *= SC;
                mx = fmaxf(mx, fmaxf(s[j][2 * hf], s[j][2 * hf + 1]));
            }
            mx = fmaxf(mx, __shfl_xor_sync(0xffffffffu, mx, 1));
            mx = fmaxf(mx, __shfl_xor_sync(0xffffffffu, mx, 2));
            const float nm = fmaxf(mrun[hf], mx);
            corrB[hf] = fast_exp2(mrun[hf] - nm);
            mrun[hf] = nm;
            float sum = 0.0f;
            #pragma unroll
            for (int j = 4; j < 8; j++) {
                const float p0 = fast_exp2(s[j][2 * hf] - nm);
                const float p1 = fast_exp2(s[j][2 * hf + 1] - nm);
                s[j][2 * hf] = p0;
                s[j][2 * hf + 1] = p1;
                sum += p0 + p1;
            }
            sum += __shfl_xor_sync(0xffffffffu, sum, 1);
            sum += __shfl_xor_sync(0xffffffffu, sum, 2);
            lrun[hf] = lrun[hf] * corrB[hf] + sum;
        }

        // ---- PV_A: O += P_A @ V[0:32] ----
        #pragma unroll
        for (int j = 0; j < 4; j++) {
            uint32_t pa[4];
            pa[0] = f2tf(s[j][0]);
            pa[1] = f2tf(s[j][2]);
            pa[2] = f2tf(s[j][1]);
            pa[3] = f2tf(s[j][3]);
            #pragma unroll
            for (int jj = 0; jj < 4; jj++) {
                uint32_t bfr[4];
                ldsm4(bfr, vbs + j * 32 + jj * (16 * LDA * 4));
                mma_tf32(O[2 * jj],     pa, bfr[0], bfr[1]);
                mma_tf32(O[2 * jj + 1], pa, bfr[2], bfr[3]);
            }
        }

        // ---- O *= corr_B ----
        #pragma unroll
        for (int hf = 0; hf < 2; hf++)
            #pragma unroll
            for (int j = 0; j < 8; j++) {
                O[j][2 * hf]     *= corrB[hf];
                O[j][2 * hf + 1] *= corrB[hf];
            }

        // ---- PV_B: O += P_B @ V[32:64] ----
        #pragma unroll
        for (int j = 4; j < 8; j++) {
            uint32_t pa[4];
            pa[0] = f2tf(s[j][0]);
            pa[1] = f2tf(s[j][2]);
            pa[2] = f2tf(s[j][1]);
            pa[3] = f2tf(s[j][3]);
            #pragma unroll
            for (int jj = 0; jj < 4; jj++) {
                uint32_t bfr[4];
                ldsm4(bfr, vbs + j * 32 + jj * (16 * LDA * 4));
                mma_tf32(O[2 * jj],     pa, bfr[0], bfr[1]);
                mma_tf32(O[2 * jj + 1], pa, bfr[2], bfr[3]);
            }
        }
    }

    // normalize + store (rounded for the proj GEMM)
    #pragma unroll
    for (int hf = 0; hf < 2; hf++) {
        const float linv = 1.0f / lrun[hf];
        const int row = q0 + mb + g + 8 * hf;
        #pragma unroll
        for (int j = 0; j < 8; j++) {
            const int col = h * 64 + 8 * j + 2 * tig;
            *(float2*)&g_attn[(size_t)(b * 1024 + row) * 768 + col] =
                make_float2(__uint_as_float(f2tf(O[j][2 * hf] * linv)),
                            __uint_as_float(f2tf(O[j][2 * hf + 1] * linv)));
        }
    }
}

// ---------------------------------------------------------------------------
// Launch
// ---------------------------------------------------------------------------
extern "C" void kernel_launch(void* const* d_in, const int* in_sizes, int n_in,
                              void* d_out, int out_size)
{
    const float* x     = (const float*)d_in[0];
    const float* Wqkv  = (const float*)d_in[1];
    const float* bqkv  = (const float*)d_in[2];
    const float* Wproj = (const float*)d_in[3];
    const float* bproj = (const float*)d_in[4];
    float* out = (float*)d_out;

    float *qkv, *attn, *xr, *wqkvr, *wprojr;
    cudaGetSymbolAddress((void**)&qkv,    g_qkv);
    cudaGetSymbolAddress((void**)&attn,   g_attn);
    cudaGetSymbolAddress((void**)&xr,     g_xr);
    cudaGetSymbolAddress((void**)&wqkvr,  g_wqkvr);
    cudaGetSymbolAddress((void**)&wprojr, g_wprojr);

    const int gemm_smem = 3 * 32768;                        // 98304 B
    const int attn_smem = 68 * (128 + 128 + 128) * 4;       // 104448 B
    static bool attr_done = false;
    if (!attr_done) {
        cudaFuncSetAttribute(gemm_tf32_kernel,
                             cudaFuncAttributeMaxDynamicSharedMemorySize, gemm_smem);
        cudaFuncSetAttribute(attn_tf32_kernel,
                             cudaFuncAttributeMaxDynamicSharedMemorySize, attn_smem);
        attr_done = true;
    }

    // 0) round inputs to tf32-rna
    round_tf32_kernel<<<(8192 * 768 / 4 + 255) / 256, 256>>>(x, xr, 8192 * 768 / 4);
    round_tf32_kernel<<<(2304 * 768 / 4 + 255) / 256, 256>>>(Wqkv, wqkvr, 2304 * 768 / 4);
    round_tf32_kernel<<<(768 * 768 / 4 + 255) / 256, 256>>>(Wproj, wprojr, 768 * 768 / 4);

    {   // QKV: [8192,768] @ [2304,768]^T + b   (round outputs for attention)
        dim3 grid(2304 / 128, 8192 / 128);
        gemm_tf32_kernel<<<grid, 256, gemm_smem>>>(xr, wqkvr, bqkv, qkv, 8192, 2304, 768, 1);
    }
    {   // attention
        attn_tf32_kernel<<<768, 256, attn_smem>>>();
    }
    {   // proj: [8192,768] @ [768,768]^T + b   (final output, no rounding)
        dim3 grid(768 / 128, 8192 / 128);
        gemm_tf32_kernel<<<grid, 256, gemm_smem>>>(attn, wprojr, bproj, out, 8192, 768, 768, 0);
    }
}

// round 13
// speedup vs baseline: 1.1106x; 1.0503x over previous
#include <cuda_runtime.h>
#include <cuda_bf16.h>
#include <cstdint>

// Problem: B=8, N=1024, D=768, H=12, Hd=64
__device__ float g_qkv[8192 * 2304];    // rounded tf32 bits after QKV gemm
__device__ float g_attn[8192 * 768];    // rounded tf32 bits after attention
__device__ float g_xr[8192 * 768];      // x rounded to tf32-rna
__device__ float g_wqkvr[2304 * 768];   // W_qkv rounded
__device__ float g_wprojr[768 * 768];   // W_proj rounded

// ---------------------------------------------------------------------------
// helpers
// ---------------------------------------------------------------------------
__device__ __forceinline__ uint32_t f2tf(float f) {
    uint32_t u;
    asm("cvt.rna.tf32.f32 %0, %1;" : "=r"(u) : "f"(f));
    return u;
}

__device__ __forceinline__ void mma_tf32(float c[4],
                                         const uint32_t a[4],
                                         uint32_t b0, uint32_t b1) {
    asm volatile(
        "mma.sync.aligned.m16n8k8.row.col.f32.tf32.tf32.f32 "
        "{%0,%1,%2,%3}, {%4,%5,%6,%7}, {%8,%9}, {%0,%1,%2,%3};"
        : "+f"(c[0]), "+f"(c[1]), "+f"(c[2]), "+f"(c[3])
        : "r"(a[0]), "r"(a[1]), "r"(a[2]), "r"(a[3]), "r"(b0), "r"(b1));
}

__device__ __forceinline__ void ldsm4(uint32_t r[4], uint32_t addr) {
    asm volatile("ldmatrix.sync.aligned.m8n8.x4.shared.b16 {%0,%1,%2,%3}, [%4];"
                 : "=r"(r[0]), "=r"(r[1]), "=r"(r[2]), "=r"(r[3]) : "r"(addr));
}

__device__ __forceinline__ void cpasync16(uint32_t dst, const void* src) {
    asm volatile("cp.async.cg.shared.global [%0], [%1], 16;" :: "r"(dst), "l"(src));
}
__device__ __forceinline__ void cp_commit() {
    asm volatile("cp.async.commit_group;");
}
template <int N>
__device__ __forceinline__ void cp_wait() {
    asm volatile("cp.async.wait_group %0;" :: "n"(N));
}

__device__ __forceinline__ float fast_exp2(float x) {
    float y;
    asm("ex2.approx.ftz.f32 %0, %1;" : "=f"(y) : "f"(x));
    return y;
}

// ---------------------------------------------------------------------------
// Fused pre-pass: round x, W_qkv, W_proj to tf32-rna in ONE launch.
// n4 counts (float4 units): x 1572864, Wqkv 442368, Wproj 147456.
// ---------------------------------------------------------------------------
__global__ __launch_bounds__(256) void round_all_kernel(
    const float* __restrict__ x,     float* __restrict__ xr,
    const float* __restrict__ wqkv,  float* __restrict__ wqkvr,
    const float* __restrict__ wproj, float* __restrict__ wprojr)
{
    constexpr int N4_X  = 8192 * 768 / 4;   // 1572864
    constexpr int N4_WQ = 2304 * 768 / 4;   //  442368
    constexpr int N4_WP =  768 * 768 / 4;   //  147456
    const int i = blockIdx.x * 256 + threadIdx.x;

    const float4* src;
    uint4* dst;
    int idx;
    if (i < N4_X) {
        src = (const float4*)x;      dst = (uint4*)xr;     idx = i;
    } else if (i < N4_X + N4_WQ) {
        src = (const float4*)wqkv;   dst = (uint4*)wqkvr;  idx = i - N4_X;
    } else if (i < N4_X + N4_WQ + N4_WP) {
        src = (const float4*)wproj;  dst = (uint4*)wprojr; idx = i - N4_X - N4_WQ;
    } else {
        return;
    }
    const float4 v = src[idx];
    dst[idx] = make_uint4(f2tf(v.x), f2tf(v.y), f2tf(v.z), f2tf(v.w));
}

// ---------------------------------------------------------------------------
// TF32 GEMM: C[M,N] = A[M,K] @ W[N,K]^T + bias[N]
// R5 configuration (proven 159 us): 128x128 CTA tile, warp 32x64, BK=32,
// 3-stage cp.async ring, SW128 swizzle, 2 CTAs/SM.
// ---------------------------------------------------------------------------
__global__ __launch_bounds__(256, 2) void gemm_tf32_kernel(
    const float* __restrict__ A, const float* __restrict__ W,
    const float* __restrict__ bias, float* __restrict__ C,
    int M, int N, int K, int roundOut)
{
    extern __shared__ uint32_t sm[];
    constexpr int STG_B = 32768;

    const int tid  = threadIdx.x;
    const int lane = tid & 31;
    const int wrp  = tid >> 5;
    const int wm   = wrp & 3;
    const int wn   = wrp >> 2;
    const int g    = lane >> 2;
    const int tig  = lane & 3;

    const int m0 = blockIdx.y * 128;
    const int n0 = blockIdx.x * 128;

    const uint32_t smb = (uint32_t)__cvta_generic_to_shared(sm);

    const int row0 = tid >> 3;
    const int cch  = tid & 7;
    const uint32_t dsw = (uint32_t)((cch ^ (row0 & 7)) << 4);
    const float* srcA = A + (size_t)(m0 + row0) * K + cch * 4;
    const float* srcW = W + (size_t)(n0 + row0) * K + cch * 4;

    const int rowA = 32 * wm + (lane & 15);
    const uint32_t rbA = (uint32_t)(rowA * 128);
    const uint32_t rxA = (uint32_t)((rowA & 7) << 4);
    const int hiA = lane >> 4;
    const int rowB = 64 * wn + (lane & 7) + ((lane >> 4) & 1) * 8;
    const uint32_t rbB = (uint32_t)(rowB * 128);
    const uint32_t rxB = (uint32_t)((rowB & 7) << 4);
    const int hiB = (lane >> 3) & 1;

    float acc[2][8][4];
    #pragma unroll
    for (int i = 0; i < 2; i++)
        #pragma unroll
        for (int j = 0; j < 8; j++)
            #pragma unroll
            for (int c = 0; c < 4; c++) acc[i][j][c] = 0.0f;

    const int NK = K >> 5;

    #pragma unroll
    for (int s = 0; s < 2; s++) {
        const uint32_t sb = smb + s * STG_B;
        #pragma unroll
        for (int i = 0; i < 4; i++) {
            const uint32_t d = sb + (uint32_t)((row0 + 32 * i) * 128) + dsw;
            cpasync16(d,         srcA + s * 32 + (size_t)(32 * i) * K);
            cpasync16(d + 16384, srcW + s * 32 + (size_t)(32 * i) * K);
        }
        cp_commit();
    }

    int stage = 0;
    for (int t = 0; t < NK; t++) {
        cp_wait<1>();
        __syncthreads();

        if (t + 2 < NK) {
            const int s = (stage + 2 >= 3) ? stage - 1 : stage + 2;
            const uint32_t sb = smb + s * STG_B;
            const int kofs = (t + 2) * 32;
            #pragma unroll
            for (int i = 0; i < 4; i++) {
                const uint32_t d = sb + (uint32_t)((row0 + 32 * i) * 128) + dsw;
                cpasync16(d,         srcA + kofs + (size_t)(32 * i) * K);
                cpasync16(d + 16384, srcW + kofs + (size_t)(32 * i) * K);
            }
        }
        cp_commit();

        const uint32_t sA = smb + stage * STG_B;
        const uint32_t sB = sA + 16384;
        #pragma unroll
        for (int ks = 0; ks < 4; ks++) {
            uint32_t a0[4], a1[4];
            const uint32_t ca = ((uint32_t)((2 * ks + hiA) << 4)) ^ rxA;
            ldsm4(a0, sA + rbA + ca);
            ldsm4(a1, sA + rbA + ca + 2048);
            const uint32_t cb = ((uint32_t)((2 * ks + hiB) << 4)) ^ rxB;
            #pragma unroll
            for (int jj = 0; jj < 4; jj++) {
                uint32_t b[4];
                ldsm4(b, sB + rbB + jj * 2048 + cb);
                mma_tf32(acc[0][2 * jj],     a0, b[0], b[1]);
                mma_tf32(acc[1][2 * jj],     a1, b[0], b[1]);
                mma_tf32(acc[0][2 * jj + 1], a0, b[2], b[3]);
                mma_tf32(acc[1][2 * jj + 1], a1, b[2], b[3]);
            }
        }
        stage = (stage + 1 >= 3) ? 0 : stage + 1;
    }

    #pragma unroll
    for (int j = 0; j < 8; j++) {
        const int col = n0 + 64 * wn + 8 * j + 2 * tig;
        const float b0 = bias[col];
        const float b1 = bias[col + 1];
        #pragma unroll
        for (int i = 0; i < 2; i++) {
            const int row = m0 + 32 * wm + 16 * i + g;
            float v0 = acc[i][j][0] + b0, v1 = acc[i][j][1] + b1;
            float v2 = acc[i][j][2] + b0, v3 = acc[i][j][3] + b1;
            if (roundOut) {
                v0 = __uint_as_float(f2tf(v0));
                v1 = __uint_as_float(f2tf(v1));
                v2 = __uint_as_float(f2tf(v2));
                v3 = __uint_as_float(f2tf(v3));
            }
            *(float2*)&C[(size_t)row * N + col]       = make_float2(v0, v1);
            *(float2*)&C[(size_t)(row + 8) * N + col] = make_float2(v2, v3);
        }
    }
}

// ---------------------------------------------------------------------------
// TF32 flash attention — EXACT R9 version (best measured: 414.6 total).
// 256 threads (8 warps x 16 q-rows), 128 queries/block, split 64-key tiles
// (softmax_A || S_B, softmax_B || PV_A), Q frags reloaded per tile,
// P in registers via key permutation sigma(2t+e)=t+4e baked into Vt.
// ---------------------------------------------------------------------------
__global__ __launch_bounds__(256, 2) void attn_tf32_kernel()
{
    extern __shared__ uint32_t sm[];
    constexpr int LDA = 68;
    constexpr int VT_U32 = 17408;
    constexpr int STG_U32 = 4352;
    constexpr int STG_BYTE = 17408;

    const int tid  = threadIdx.x;
    const int lane = tid & 31;
    const int wrp  = tid >> 5;
    const int g    = lane >> 2;
    const int tig  = lane & 3;

    const int qtile = blockIdx.x & 7;
    const int bh    = blockIdx.x >> 3;
    const int h     = bh % 12;
    const int b     = bh / 12;
    const int q0    = qtile * 128;
    const int mb    = 16 * wrp;

    const uint32_t smb = (uint32_t)__cvta_generic_to_shared(sm);
    const uint32_t qaBase = smb + (((mb + (lane & 15)) * LDA + (lane >> 4) * 4) << 2);
    const uint32_t bRow = (((lane & 7) + ((lane >> 4) & 1) * 8) * LDA + ((lane >> 3) & 1) * 4) << 2;
    const uint32_t kbBase = smb + 34816 + bRow;
    const uint32_t vbBase = smb + 69632 + bRow;

    const size_t tokBase = (size_t)(b * 1024) * 2304 + h * 64;

    // stage Q [128][64] to smem (persistent; frags reloaded per tile)
    #pragma unroll
    for (int it = 0; it < 8; it++) {
        const int e   = tid + it * 256;
        const int row = e >> 4;
        const int c4  = (e & 15) * 4;
        *(float4*)&sm[row * LDA + c4] =
            *(const float4*)&g_qkv[tokBase + (size_t)(q0 + row) * 2304 + c4];
    }

    float O[8][4];
    #pragma unroll
    for (int j = 0; j < 8; j++)
        #pragma unroll
        for (int c = 0; c < 4; c++) O[j][c] = 0.0f;
    float mrun[2] = {-1e30f, -1e30f}, lrun[2] = {0.0f, 0.0f};

    const float SC = 0.18033688011112042f;   // 0.125 * log2(e)

    const int vhd  = tid & 63;
    const int vkg  = tid >> 6;

    // prologue: K0 via cp.async, V0 gather-transpose
    #pragma unroll
    for (int it = 0; it < 4; it++) {
        const int e   = tid + it * 256;
        const int key = e >> 4;
        const int c   = e & 15;
        cpasync16(smb + 34816 + (uint32_t)((key * LDA + c * 4) << 2),
                  &g_qkv[tokBase + (size_t)key * 2304 + 768 + c * 4]);
    }
    cp_commit();
    #pragma unroll
    for (int it = 0; it < 4; it++) {
        const int kg  = vkg + it * 4;
        const int grp = kg >> 1;
        const int ee  = kg & 1;
        const size_t vb = tokBase + (size_t)(8 * grp + ee) * 2304 + 1536 + vhd;
        float4 v;
        v.x = g_qkv[vb];
        v.y = g_qkv[vb + 2 * 2304];
        v.z = g_qkv[vb + 4 * 2304];
        v.w = g_qkv[vb + 6 * 2304];
        *(float4*)&sm[VT_U32 + vhd * LDA + 8 * grp + 4 * ee] = v;
    }

    for (int t = 0; t < 16; t++) {
        const int cur = t & 1;
        const int nxt = cur ^ 1;
        const int tn  = (t + 1 < 16) ? t + 1 : 15;

        cp_wait<0>();
        __syncthreads();

        // prefetch next K (async) + next-V gather loads
        const size_t nb = tokBase + (size_t)(tn * 64) * 2304;
        #pragma unroll
        for (int it = 0; it < 4; it++) {
            const int e   = tid + it * 256;
            const int key = e >> 4;
            const int c   = e & 15;
            cpasync16(smb + 34816 + (uint32_t)(nxt * STG_BYTE) +
                          (uint32_t)((key * LDA + c * 4) << 2),
                      &g_qkv[nb + (size_t)key * 2304 + 768 + c * 4]);
        }
        cp_commit();
        float4 gv[4];
        #pragma unroll
        for (int it = 0; it < 4; it++) {
            const int kg  = vkg + it * 4;
            const int grp = kg >> 1;
            const int ee  = kg & 1;
            const size_t vb = nb + (size_t)(8 * grp + ee) * 2304 + 1536 + vhd;
            gv[it].x = g_qkv[vb];
            gv[it].y = g_qkv[vb + 2 * 2304];
            gv[it].z = g_qkv[vb + 4 * 2304];
            gv[it].w = g_qkv[vb + 6 * 2304];
        }

        const uint32_t kb  = kbBase + cur * STG_BYTE;
        const uint32_t vbs = vbBase + cur * STG_BYTE;

        float s[8][4];
        #pragma unroll
        for (int j = 0; j < 8; j++)
            #pragma unroll
            for (int c = 0; c < 4; c++) s[j][c] = 0.0f;

        // ---- S_A: keys 0..31 ----
        #pragma unroll
        for (int ks = 0; ks < 8; ks++) {
            uint32_t qa[4];
            ldsm4(qa, qaBase + ks * 32);
            #pragma unroll
            for (int jj = 0; jj < 2; jj++) {
                uint32_t bfr[4];
                ldsm4(bfr, kb + ks * 32 + jj * (16 * LDA * 4));
                mma_tf32(s[2 * jj],     qa, bfr[0], bfr[1]);
                mma_tf32(s[2 * jj + 1], qa, bfr[2], bfr[3]);
            }
        }

        // ---- softmax_A (full, incl. O-rescale) — interleaves with S_B ----
        #pragma unroll
        for (int hf = 0; hf < 2; hf++) {
            float mx = -1e30f;
            #pragma unroll
            for (int j = 0; j < 4; j++) {
                s[j][2 * hf]     *= SC;
                s[j][2 * hf + 1] *= SC;
                mx = fmaxf(mx, fmaxf(s[j][2 * hf], s[j][2 * hf + 1]));
            }
            mx = fmaxf(mx, __shfl_xor_sync(0xffffffffu, mx, 1));
            mx = fmaxf(mx, __shfl_xor_sync(0xffffffffu, mx, 2));
            const float nm   = fmaxf(mrun[hf], mx);
            const float corr = fast_exp2(mrun[hf] - nm);
            mrun[hf] = nm;
            float sum = 0.0f;
            #pragma unroll
            for (int j = 0; j < 4; j++) {
                const float p0 = fast_exp2(s[j][2 * hf] - nm);
                const float p1 = fast_exp2(s[j][2 * hf + 1] - nm);
                s[j][2 * hf] = p0;
                s[j][2 * hf + 1] = p1;
                sum += p0 + p1;
            }
            sum += __shfl_xor_sync(0xffffffffu, sum, 1);
            sum += __shfl_xor_sync(0xffffffffu, sum, 2);
            lrun[hf] = lrun[hf] * corr + sum;
            #pragma unroll
            for (int j = 0; j < 8; j++) {
                O[j][2 * hf]     *= corr;
                O[j][2 * hf + 1] *= corr;
            }
        }

        // ---- S_B: keys 32..63 ----
        #pragma unroll
        for (int ks = 0; ks < 8; ks++) {
            uint32_t qa[4];
            ldsm4(qa, qaBase + ks * 32);
            #pragma unroll
            for (int jj = 2; jj < 4; jj++) {
                uint32_t bfr[4];
                ldsm4(bfr, kb + ks * 32 + jj * (16 * LDA * 4));
                mma_tf32(s[2 * jj],     qa, bfr[0], bfr[1]);
                mma_tf32(s[2 * jj + 1], qa, bfr[2], bfr[3]);
            }
        }

        // ---- store next-V transpose ----
        #pragma unroll
        for (int it = 0; it < 4; it++) {
            const int kg  = vkg + it * 4;
            const int grp = kg >> 1;
            const int ee  = kg & 1;
            *(float4*)&sm[VT_U32 + nxt * STG_U32 + vhd * LDA + 8 * grp + 4 * ee] = gv[it];
        }

        // ---- softmax_B compute (no O-rescale yet) — interleaves with PV_A ----
        float corrB[2];
        #pragma unroll
        for (int hf = 0; hf < 2; hf++) {
            float mx = -1e30f;
            #pragma unroll
            for (int j = 4; j < 8; j++) {
                s[j][2 * hf]     *= SC;
                s[j][2 * hf + 1] *= SC;
                mx = fmaxf(mx, fmaxf(s[j][2 * hf], s[j][2 * hf + 1]));
            }
            mx = fmaxf(mx, __shfl_xor_sync(0xffffffffu, mx, 1));
            mx = fmaxf(mx, __shfl_xor_sync(0xffffffffu, mx, 2));
            const float nm = fmaxf(mrun[hf], mx);
            corrB[hf] = fast_exp2(mrun[hf] - nm);
            mrun[hf] = nm;
            float sum = 0.0f;
            #pragma unroll
            for (int j = 4; j < 8; j++) {
                const float p0 = fast_exp2(s[j][2 * hf] - nm);
                const float p1 = fast_exp2(s[j][2 * hf + 1] - nm);
                s[j][2 * hf] = p0;
                s[j][2 * hf + 1] = p1;
                sum += p0 + p1;
            }
            sum += __shfl_xor_sync(0xffffffffu, sum, 1);
            sum += __shfl_xor_sync(0xffffffffu, sum, 2);
            lrun[hf] = lrun[hf] * corrB[hf] + sum;
        }

        // ---- PV_A: O += P_A @ V[0:32] ----
        #pragma unroll
        for (int j = 0; j < 4; j++) {
            uint32_t pa[4];
            pa[0] = f2tf(s[j][0]);
            pa[1] = f2tf(s[j][2]);
            pa[2] = f2tf(s[j][1]);
            pa[3] = f2tf(s[j][3]);
            #pragma unroll
            for (int jj = 0; jj < 4; jj++) {
                uint32_t bfr[4];
                ldsm4(bfr, vbs + j * 32 + jj * (16 * LDA * 4));
                mma_tf32(O[2 * jj],     pa, bfr[0], bfr[1]);
                mma_tf32(O[2 * jj + 1], pa, bfr[2], bfr[3]);
            }
        }

        // ---- O *= corr_B ----
        #pragma unroll
        for (int hf = 0; hf < 2; hf++)
            #pragma unroll
            for (int j = 0; j < 8; j++) {
                O[j][2 * hf]     *= corrB[hf];
                O[j][2 * hf + 1] *= corrB[hf];
            }

        // ---- PV_B: O += P_B @ V[32:64] ----
        #pragma unroll
        for (int j = 4; j < 8; j++) {
            uint32_t pa[4];
            pa[0] = f2tf(s[j][0]);
            pa[1] = f2tf(s[j][2]);
            pa[2] = f2tf(s[j][1]);
            pa[3] = f2tf(s[j][3]);
            #pragma unroll
            for (int jj = 0; jj < 4; jj++) {
                uint32_t bfr[4];
                ldsm4(bfr, vbs + j * 32 + jj * (16 * LDA * 4));
                mma_tf32(O[2 * jj],     pa, bfr[0], bfr[1]);
                mma_tf32(O[2 * jj + 1], pa, bfr[2], bfr[3]);
            }
        }
    }

    // normalize + store (rounded for the proj GEMM)
    #pragma unroll
    for (int hf = 0; hf < 2; hf++) {
        const float linv = 1.0f / lrun[hf];
        const int row = q0 + mb + g + 8 * hf;
        #pragma unroll
        for (int j = 0; j < 8; j++) {
            const int col = h * 64 + 8 * j + 2 * tig;
            *(float2*)&g_attn[(size_t)(b * 1024 + row) * 768 + col] =
                make_float2(__uint_as_float(f2tf(O[j][2 * hf] * linv)),
                            __uint_as_float(f2tf(O[j][2 * hf + 1] * linv)));
        }
    }
}

// ---------------------------------------------------------------------------
// Launch
// ---------------------------------------------------------------------------
extern "C" void kernel_launch(void* const* d_in, const int* in_sizes, int n_in,
                              void* d_out, int out_size)
{
    const float* x     = (const float*)d_in[0];
    const float* Wqkv  = (const float*)d_in[1];
    const float* bqkv  = (const float*)d_in[2];
    const float* Wproj = (const float*)d_in[3];
    const float* bproj = (const float*)d_in[4];
    float* out = (float*)d_out;

    float *qkv, *attn, *xr, *wqkvr, *wprojr;
    cudaGetSymbolAddress((void**)&qkv,    g_qkv);
    cudaGetSymbolAddress((void**)&attn,   g_attn);
    cudaGetSymbolAddress((void**)&xr,     g_xr);
    cudaGetSymbolAddress((void**)&wqkvr,  g_wqkvr);
    cudaGetSymbolAddress((void**)&wprojr, g_wprojr);

    const int gemm_smem = 3 * 32768;                        // 98304 B
    const int attn_smem = 68 * (128 + 128 + 128) * 4;       // 104448 B
    static bool attr_done = false;
    if (!attr_done) {
        cudaFuncSetAttribute(gemm_tf32_kernel,
                             cudaFuncAttributeMaxDynamicSharedMemorySize, gemm_smem);
        cudaFuncSetAttribute(attn_tf32_kernel,
                             cudaFuncAttributeMaxDynamicSharedMemorySize, attn_smem);
        attr_done = true;
    }

    // 0) round all inputs to tf32-rna in ONE launch
    {
        const int n4_total = 8192 * 768 / 4 + 2304 * 768 / 4 + 768 * 768 / 4;
        round_all_kernel<<<(n4_total + 255) / 256, 256>>>(
            x, xr, Wqkv, wqkvr, Wproj, wprojr);
    }

    {   // QKV: [8192,768] @ [2304,768]^T + b   (round outputs for attention)
        dim3 grid(2304 / 128, 8192 / 128);
        gemm_tf32_kernel<<<grid, 256, gemm_smem>>>(xr, wqkvr, bqkv, qkv, 8192, 2304, 768, 1);
    }
    {   // attention
        attn_tf32_kernel<<<768, 256, attn_smem>>>();
    }
    {   // proj: [8192,768] @ [768,768]^T + b   (final output, no rounding)
        dim3 grid(768 / 128, 8192 / 128);
        gemm_tf32_kernel<<<grid, 256, gemm_smem>>>(attn, wprojr, bproj, out, 8192, 768, 768, 0);
    }
}